// round 1
// baseline (speedup 1.0000x reference)
#include <cuda_runtime.h>
#include <math.h>

#define B_    4
#define S_    2048
#define DM    1024
#define NH    16
#define DK    64
#define INNER 1024

// ---------------- scratch (static device globals; no allocation) ----------------
__device__ float g_q[(size_t)B_ * NH * S_ * DK];     // [B,H,S,DK]
__device__ float g_k[(size_t)B_ * NH * S_ * DK];
__device__ float g_v[(size_t)B_ * NH * S_ * DK];
__device__ float g_ctx[(size_t)B_ * S_ * INNER];     // [B,S,H*DK]
__device__ unsigned char g_bucket[(size_t)B_ * S_ * S_];  // [B,Sq,Sk], bucket < 32

// ---------------- bucket precompute (matches T5 _relative_position_bucket, fp32 op order) ----
__global__ void bucket_kernel(const int* __restrict__ pos) {
    int idx = blockIdx.x * blockDim.x + threadIdx.x;
    if (idx >= B_ * S_ * S_) return;
    int k = idx & (S_ - 1);
    int q = (idx >> 11) & (S_ - 1);
    int b = idx >> 22;
    int rel = pos[b * S_ + k] - pos[b * S_ + q];   // memory - context
    int ret = (rel > 0) ? 16 : 0;
    int rp = rel < 0 ? -rel : rel;
    int bucket;
    if (rp < 8) {
        bucket = rp;
    } else {
        // replicate: log(rp/8) / np.log(16.0) * 8, all fp32, truncate
        float v = logf((float)rp * 0.125f);
        v = v / 2.772588722239781f;   // compiler rounds to f32 == 4*ln2f (exact at boundaries)
        v = v * 8.0f;
        bucket = 8 + (int)v;
        bucket = bucket < 15 ? bucket : 15;
    }
    g_bucket[idx] = (unsigned char)(ret + bucket);
}

// ---------------- fp32 SGEMM 128x64x16, C = A[M,K] @ W[N,K]^T ----------------
// 256 threads, 8x4 per thread. As/Bs staged transposed+padded -> conflict-free frags.
#define BM 128
#define BN 64
#define BK 16

__device__ __forceinline__ void gemm_body(const float* __restrict__ A,
                                          const float* __restrict__ W,
                                          int m0, int n0,
                                          float (&acc)[8][4],
                                          float (*As)[BM + 4], float (*Bs)[BN + 4]) {
    int tid = threadIdx.x;
    int tx = tid & 15, ty = tid >> 4;
    for (int k0 = 0; k0 < DM; k0 += BK) {
        #pragma unroll
        for (int i = 0; i < 2; i++) {
            int idx = tid + i * 256;
            int r = idx >> 2, c4 = idx & 3;
            float4 va = *(const float4*)&A[(size_t)(m0 + r) * DM + k0 + c4 * 4];
            As[c4 * 4 + 0][r] = va.x; As[c4 * 4 + 1][r] = va.y;
            As[c4 * 4 + 2][r] = va.z; As[c4 * 4 + 3][r] = va.w;
        }
        {
            int r = tid >> 2, c4 = tid & 3;
            float4 vb = *(const float4*)&W[(size_t)(n0 + r) * DM + k0 + c4 * 4];
            Bs[c4 * 4 + 0][r] = vb.x; Bs[c4 * 4 + 1][r] = vb.y;
            Bs[c4 * 4 + 2][r] = vb.z; Bs[c4 * 4 + 3][r] = vb.w;
        }
        __syncthreads();
        #pragma unroll
        for (int kk = 0; kk < BK; kk++) {
            float4 a0 = *(const float4*)&As[kk][ty * 8];
            float4 a1 = *(const float4*)&As[kk][ty * 8 + 4];
            float4 bb = *(const float4*)&Bs[kk][tx * 4];
            float a[8] = {a0.x, a0.y, a0.z, a0.w, a1.x, a1.y, a1.z, a1.w};
            float bv[4] = {bb.x, bb.y, bb.z, bb.w};
            #pragma unroll
            for (int i = 0; i < 8; i++)
                #pragma unroll
                for (int j = 0; j < 4; j++)
                    acc[i][j] += a[i] * bv[j];
        }
        __syncthreads();
    }
}

// QKV projection: z selects (wq->g_q, wk->g_k, wv->g_v); stores into [B,H,S,DK]
__global__ __launch_bounds__(256) void proj_kernel(const float* __restrict__ A,
                                                   const float* __restrict__ wq,
                                                   const float* __restrict__ wk,
                                                   const float* __restrict__ wv) {
    __shared__ float As[BK][BM + 4];
    __shared__ float Bs[BK][BN + 4];
    const float* W = (blockIdx.z == 0) ? wq : (blockIdx.z == 1) ? wk : wv;
    float* C = (blockIdx.z == 0) ? g_q : (blockIdx.z == 1) ? g_k : g_v;
    int m0 = blockIdx.y * BM, n0 = blockIdx.x * BN;
    float acc[8][4] = {};
    gemm_body(A, W, m0, n0, acc, As, Bs);
    int tx = threadIdx.x & 15, ty = threadIdx.x >> 4;
    int h = n0 >> 6;
    #pragma unroll
    for (int i = 0; i < 8; i++) {
        int m = m0 + ty * 8 + i;
        int bb = m >> 11, s = m & (S_ - 1);
        float4 v = {acc[i][0], acc[i][1], acc[i][2], acc[i][3]};
        *(float4*)&C[(((size_t)(bb * NH + h) * S_ + s) << 6) + tx * 4] = v;
    }
}

// Output projection: out = g_ctx @ wo^T, row-major [B*S, DM]
__global__ __launch_bounds__(256) void outproj_kernel(const float* __restrict__ wo,
                                                      float* __restrict__ out) {
    __shared__ float As[BK][BM + 4];
    __shared__ float Bs[BK][BN + 4];
    int m0 = blockIdx.y * BM, n0 = blockIdx.x * BN;
    float acc[8][4] = {};
    gemm_body(g_ctx, wo, m0, n0, acc, As, Bs);
    int tx = threadIdx.x & 15, ty = threadIdx.x >> 4;
    #pragma unroll
    for (int i = 0; i < 8; i++) {
        int m = m0 + ty * 8 + i;
        float4 v = {acc[i][0], acc[i][1], acc[i][2], acc[i][3]};
        *(float4*)&out[(size_t)m * DM + n0 + tx * 4] = v;
    }
}

// ---------------- flash attention fp32, 64x64 tiles, online softmax ----------------
// grid: (S/64, NH, B), 256 threads (16x16), 4x4 per thread.
#define PAD 68  // 64+4 row pad

__global__ __launch_bounds__(256) void attn_kernel(const float* __restrict__ rel_bias,
                                                   const float* __restrict__ mask) {
    extern __shared__ float sm[];
    float* Qs  = sm;                    // [64][PAD] natural (row=q, col=d)
    float* Kt  = Qs + 64 * PAD;         // [64][PAD] transposed (row=d, col=k)
    float* Vs  = Kt + 64 * PAD;         // [64][64]  natural (row=k, col=d)
    float* Ps  = Vs + 64 * 64;          // [64][PAD] natural (row=q, col=k)
    float* rbh = Ps + 64 * PAD;         // [32] per-head bias LUT
    float* mcl = rbh + 32;              // [64] mask column term

    int tid = threadIdx.x;
    int tx = tid & 15, ty = tid >> 4;
    int q0 = blockIdx.x * 64, h = blockIdx.y, b = blockIdx.z;

    const float* qbase = g_q + ((size_t)(b * NH + h) * S_ + q0) * DK;
    const float* kbase = g_k + (size_t)(b * NH + h) * S_ * DK;
    const float* vbase = g_v + (size_t)(b * NH + h) * S_ * DK;
    const unsigned char* bkbase = g_bucket + ((size_t)b * S_ + q0) * S_;

    if (tid < 32) rbh[tid] = rel_bias[tid * NH + h];

    // load Q tile (natural layout)
    #pragma unroll
    for (int i = 0; i < 4; i++) {
        int idx = tid + i * 256;
        int r = idx >> 4, d4 = idx & 15;
        *(float4*)&Qs[r * PAD + d4 * 4] = *(const float4*)&qbase[r * 64 + d4 * 4];
    }

    float m_i[4], l_i[4], o[4][4];
    #pragma unroll
    for (int i = 0; i < 4; i++) {
        m_i[i] = -1e30f; l_i[i] = 0.f;
        #pragma unroll
        for (int j = 0; j < 4; j++) o[i][j] = 0.f;
    }

    for (int k0 = 0; k0 < S_; k0 += 64) {
        __syncthreads();   // previous O-gemm done reading Vs/Ps
        #pragma unroll
        for (int i = 0; i < 4; i++) {
            int idx = tid + i * 256;
            int r = idx >> 4, d4 = idx & 15;
            float4 kv = *(const float4*)&kbase[(size_t)(k0 + r) * 64 + d4 * 4];
            Kt[(d4 * 4 + 0) * PAD + r] = kv.x;
            Kt[(d4 * 4 + 1) * PAD + r] = kv.y;
            Kt[(d4 * 4 + 2) * PAD + r] = kv.z;
            Kt[(d4 * 4 + 3) * PAD + r] = kv.w;
            *(float4*)&Vs[r * 64 + d4 * 4] = *(const float4*)&vbase[(size_t)(k0 + r) * 64 + d4 * 4];
        }
        if (tid < 64) mcl[tid] = -1000.0f * (1.0f - mask[b * S_ + k0 + tid]);
        __syncthreads();

        // S = Q @ K^T (64x64, d-reduction 64)
        float s[4][4] = {};
        #pragma unroll
        for (int d = 0; d < 64; d++) {
            float a0 = Qs[(ty * 4 + 0) * PAD + d];
            float a1 = Qs[(ty * 4 + 1) * PAD + d];
            float a2 = Qs[(ty * 4 + 2) * PAD + d];
            float a3 = Qs[(ty * 4 + 3) * PAD + d];
            float4 bb = *(const float4*)&Kt[d * PAD + tx * 4];
            s[0][0] += a0 * bb.x; s[0][1] += a0 * bb.y; s[0][2] += a0 * bb.z; s[0][3] += a0 * bb.w;
            s[1][0] += a1 * bb.x; s[1][1] += a1 * bb.y; s[1][2] += a1 * bb.z; s[1][3] += a1 * bb.w;
            s[2][0] += a2 * bb.x; s[2][1] += a2 * bb.y; s[2][2] += a2 * bb.z; s[2][3] += a2 * bb.w;
            s[3][0] += a3 * bb.x; s[3][1] += a3 * bb.y; s[3][2] += a3 * bb.z; s[3][3] += a3 * bb.w;
        }

        // + position bias + mask term
        float mc0 = mcl[tx * 4 + 0], mc1 = mcl[tx * 4 + 1], mc2 = mcl[tx * 4 + 2], mc3 = mcl[tx * 4 + 3];
        #pragma unroll
        for (int i = 0; i < 4; i++) {
            uchar4 bk = *(const uchar4*)(bkbase + (size_t)(ty * 4 + i) * S_ + k0 + tx * 4);
            s[i][0] += rbh[bk.x] + mc0;
            s[i][1] += rbh[bk.y] + mc1;
            s[i][2] += rbh[bk.z] + mc2;
            s[i][3] += rbh[bk.w] + mc3;
        }

        // online softmax (row reductions across the 16-lane tx group)
        #pragma unroll
        for (int i = 0; i < 4; i++) {
            float rm = fmaxf(fmaxf(s[i][0], s[i][1]), fmaxf(s[i][2], s[i][3]));
            rm = fmaxf(rm, __shfl_xor_sync(0xffffffffu, rm, 1));
            rm = fmaxf(rm, __shfl_xor_sync(0xffffffffu, rm, 2));
            rm = fmaxf(rm, __shfl_xor_sync(0xffffffffu, rm, 4));
            rm = fmaxf(rm, __shfl_xor_sync(0xffffffffu, rm, 8));
            float mn = fmaxf(m_i[i], rm);
            float fac = __expf(m_i[i] - mn);
            m_i[i] = mn;
            float p0 = __expf(s[i][0] - mn);
            float p1 = __expf(s[i][1] - mn);
            float p2 = __expf(s[i][2] - mn);
            float p3 = __expf(s[i][3] - mn);
            float rs = p0 + p1 + p2 + p3;
            rs += __shfl_xor_sync(0xffffffffu, rs, 1);
            rs += __shfl_xor_sync(0xffffffffu, rs, 2);
            rs += __shfl_xor_sync(0xffffffffu, rs, 4);
            rs += __shfl_xor_sync(0xffffffffu, rs, 8);
            l_i[i] = l_i[i] * fac + rs;
            o[i][0] *= fac; o[i][1] *= fac; o[i][2] *= fac; o[i][3] *= fac;
            float4 pv = {p0, p1, p2, p3};
            *(float4*)&Ps[(ty * 4 + i) * PAD + tx * 4] = pv;
        }
        __syncthreads();   // Ps visible

        // O += P @ V (64x64, k-reduction 64)
        #pragma unroll
        for (int k = 0; k < 64; k++) {
            float a0 = Ps[(ty * 4 + 0) * PAD + k];
            float a1 = Ps[(ty * 4 + 1) * PAD + k];
            float a2 = Ps[(ty * 4 + 2) * PAD + k];
            float a3 = Ps[(ty * 4 + 3) * PAD + k];
            float4 bb = *(const float4*)&Vs[k * 64 + tx * 4];
            o[0][0] += a0 * bb.x; o[0][1] += a0 * bb.y; o[0][2] += a0 * bb.z; o[0][3] += a0 * bb.w;
            o[1][0] += a1 * bb.x; o[1][1] += a1 * bb.y; o[1][2] += a1 * bb.z; o[1][3] += a1 * bb.w;
            o[2][0] += a2 * bb.x; o[2][1] += a2 * bb.y; o[2][2] += a2 * bb.z; o[2][3] += a2 * bb.w;
            o[3][0] += a3 * bb.x; o[3][1] += a3 * bb.y; o[3][2] += a3 * bb.z; o[3][3] += a3 * bb.w;
        }
    }

    // epilogue: normalize, write ctx [B,S,H*DK]
    float* cbase = g_ctx + ((size_t)(b * S_ + q0)) * INNER + h * DK;
    #pragma unroll
    for (int i = 0; i < 4; i++) {
        float inv = 1.0f / l_i[i];
        float4 v = {o[i][0] * inv, o[i][1] * inv, o[i][2] * inv, o[i][3] * inv};
        *(float4*)&cbase[(size_t)(ty * 4 + i) * INNER + tx * 4] = v;
    }
}

// ---------------- launch ----------------
static const int ATTN_SMEM = (64 * PAD * 3 + 64 * 64 + 32 + 64) * (int)sizeof(float);

extern "C" void kernel_launch(void* const* d_in, const int* in_sizes, int n_in,
                              void* d_out, int out_size) {
    const float* hidden    = (const float*)d_in[0];
    const int*   positions = (const int*)d_in[1];
    const float* mask      = (const float*)d_in[2];
    const float* wq        = (const float*)d_in[3];
    const float* wk        = (const float*)d_in[4];
    const float* wv        = (const float*)d_in[5];
    const float* wo        = (const float*)d_in[6];
    const float* rel_bias  = (const float*)d_in[7];
    float* out = (float*)d_out;

    cudaFuncSetAttribute(attn_kernel, cudaFuncAttributeMaxDynamicSharedMemorySize, ATTN_SMEM);

    int nb = B_ * S_ * S_;
    bucket_kernel<<<(nb + 255) / 256, 256>>>(positions);

    dim3 gproj(DM / BN, (B_ * S_) / BM, 3);
    proj_kernel<<<gproj, 256>>>(hidden, wq, wk, wv);

    dim3 gattn(S_ / 64, NH, B_);
    attn_kernel<<<gattn, 256, ATTN_SMEM>>>(rel_bias, mask);

    dim3 gout(DM / BN, (B_ * S_) / BM, 1);
    outproj_kernel<<<gout, 256>>>(wo, out);
}

// round 3
// speedup vs baseline: 1.3197x; 1.3197x over previous
#include <cuda_runtime.h>
#include <cuda_bf16.h>
#include <math.h>
#include <stdint.h>

#define B_    4
#define S_    2048
#define DM    1024
#define NH    16
#define DK    64
#define INNER 1024

// ---------------- scratch (static device globals; no allocation) ----------------
__device__ float g_q[(size_t)B_ * NH * S_ * DK];     // [B,H,S,DK]
__device__ float g_k[(size_t)B_ * NH * S_ * DK];
__device__ float g_v[(size_t)B_ * NH * S_ * DK];
__device__ float g_ctx[(size_t)B_ * S_ * INNER];     // [B,S,H*DK]
__device__ unsigned char g_bucket[(size_t)B_ * S_ * S_];  // [B,Sq,Sk], bucket < 32

// ================= bucket precompute =================
__global__ void bucket_kernel(const int* __restrict__ pos) {
    int idx = blockIdx.x * blockDim.x + threadIdx.x;
    if (idx >= B_ * S_ * S_) return;
    int k = idx & (S_ - 1);
    int q = (idx >> 11) & (S_ - 1);
    int b = idx >> 22;
    int rel = pos[b * S_ + k] - pos[b * S_ + q];
    int ret = (rel > 0) ? 16 : 0;
    int rp = rel < 0 ? -rel : rel;
    int bucket;
    if (rp < 8) {
        bucket = rp;
    } else {
        float v = logf((float)rp * 0.125f);
        v = v / 2.772588722239781f;
        v = v * 8.0f;
        bucket = 8 + (int)v;
        bucket = bucket < 15 ? bucket : 15;
    }
    g_bucket[idx] = (unsigned char)(ret + bucket);
}

// ================= mma.sync bf16-split GEMM core =================
// C[M,N] = A[M,1024] @ W[N,1024]^T, block tile 128x128, 256 thr (2x4 warps),
// warp tile 64x32 (4x4 m16n8k16). Split: hi*hi + lo*hi + hi*lo.
// smem row stride 80B (40 bf16 per 32-k row) -> conflict-free fragment LDS.

#define RS 80                       // bytes per k-row (32 bf16 + pad)
#define AHI_OFF 0
#define ALO_OFF (128 * RS)
#define BHI_OFF (2 * 128 * RS)
#define BLO_OFF (3 * 128 * RS)
#define GSMEM   (4 * 128 * RS)      // 40960 B

__device__ __forceinline__ void mma16816(float* c, const uint32_t* a, const uint32_t* b) {
    asm volatile(
        "mma.sync.aligned.m16n8k16.row.col.f32.bf16.bf16.f32 "
        "{%0,%1,%2,%3}, {%4,%5,%6,%7}, {%8,%9}, {%0,%1,%2,%3};\n"
        : "+f"(c[0]), "+f"(c[1]), "+f"(c[2]), "+f"(c[3])
        : "r"(a[0]), "r"(a[1]), "r"(a[2]), "r"(a[3]), "r"(b[0]), "r"(b[1]));
}

__device__ __forceinline__ void sts_split(char* hi, char* lo, float4 v) {
    __nv_bfloat162 h0 = __floats2bfloat162_rn(v.x, v.y);
    __nv_bfloat162 h1 = __floats2bfloat162_rn(v.z, v.w);
    float lx = v.x - __bfloat162float(h0.x);
    float ly = v.y - __bfloat162float(h0.y);
    float lz = v.z - __bfloat162float(h1.x);
    float lw = v.w - __bfloat162float(h1.y);
    __nv_bfloat162 l0 = __floats2bfloat162_rn(lx, ly);
    __nv_bfloat162 l1 = __floats2bfloat162_rn(lz, lw);
    uint2 uh = {*(uint32_t*)&h0, *(uint32_t*)&h1};
    uint2 ul = {*(uint32_t*)&l0, *(uint32_t*)&l1};
    *(uint2*)hi = uh;
    *(uint2*)lo = ul;
}

__device__ __forceinline__ void mma_gemm_tile(const float* __restrict__ A,
                                              const float* __restrict__ W,
                                              int m0, int n0,
                                              float acc[4][4][4], char* smem) {
    int tid = threadIdx.x, lane = tid & 31, wid = tid >> 5;
    int wm = wid >> 2, wn = wid & 3;          // warp grid 2(m) x 4(n)
    int g = lane >> 2, tg = lane & 3;

    float4 ra[4], rb[4];
    // preload chunk 0
    #pragma unroll
    for (int j = 0; j < 4; j++) {
        int idx = tid + j * 256;
        int row = idx >> 3, c4 = idx & 7;
        ra[j] = *(const float4*)&A[((size_t)(m0 + row) << 10) + c4 * 4];
        rb[j] = *(const float4*)&W[((size_t)(n0 + row) << 10) + c4 * 4];
    }

    #pragma unroll 1
    for (int chunk = 0; chunk < 32; chunk++) {
        __syncthreads();   // previous MMA phase done reading smem
        #pragma unroll
        for (int j = 0; j < 4; j++) {
            int idx = tid + j * 256;
            int row = idx >> 3, c4 = idx & 7;
            uint32_t off = row * RS + c4 * 8;
            sts_split(smem + AHI_OFF + off, smem + ALO_OFF + off, ra[j]);
            sts_split(smem + BHI_OFF + off, smem + BLO_OFF + off, rb[j]);
        }
        __syncthreads();
        if (chunk < 31) {
            int k0 = (chunk + 1) * 32;
            #pragma unroll
            for (int j = 0; j < 4; j++) {
                int idx = tid + j * 256;
                int row = idx >> 3, c4 = idx & 7;
                ra[j] = *(const float4*)&A[((size_t)(m0 + row) << 10) + k0 + c4 * 4];
                rb[j] = *(const float4*)&W[((size_t)(n0 + row) << 10) + k0 + c4 * 4];
            }
        }
        #pragma unroll
        for (int kk = 0; kk < 2; kk++) {
            int kb = (tg * 2 + kk * 16) * 2;   // byte offset of this thread's k pair
            uint32_t bh[4][2], bl[4][2];
            #pragma unroll
            for (int nt = 0; nt < 4; nt++) {
                uint32_t off = (wn * 32 + nt * 8 + g) * RS + kb;
                bh[nt][0] = *(const uint32_t*)(smem + BHI_OFF + off);
                bh[nt][1] = *(const uint32_t*)(smem + BHI_OFF + off + 16);
                bl[nt][0] = *(const uint32_t*)(smem + BLO_OFF + off);
                bl[nt][1] = *(const uint32_t*)(smem + BLO_OFF + off + 16);
            }
            #pragma unroll
            for (int mt = 0; mt < 4; mt++) {
                uint32_t offa = (wm * 64 + mt * 16 + g) * RS + kb;
                uint32_t ah[4], al[4];
                ah[0] = *(const uint32_t*)(smem + AHI_OFF + offa);
                ah[1] = *(const uint32_t*)(smem + AHI_OFF + offa + 8 * RS);
                ah[2] = *(const uint32_t*)(smem + AHI_OFF + offa + 16);
                ah[3] = *(const uint32_t*)(smem + AHI_OFF + offa + 8 * RS + 16);
                al[0] = *(const uint32_t*)(smem + ALO_OFF + offa);
                al[1] = *(const uint32_t*)(smem + ALO_OFF + offa + 8 * RS);
                al[2] = *(const uint32_t*)(smem + ALO_OFF + offa + 16);
                al[3] = *(const uint32_t*)(smem + ALO_OFF + offa + 8 * RS + 16);
                #pragma unroll
                for (int nt = 0; nt < 4; nt++) {
                    mma16816(acc[mt][nt], ah, bh[nt]);
                    mma16816(acc[mt][nt], al, bh[nt]);
                    mma16816(acc[mt][nt], ah, bl[nt]);
                }
            }
        }
    }
}

// QKV projection. grid (24, 64): x -> (wsel, n-tile), y -> m-tile
__global__ __launch_bounds__(256) void proj_mma(const float* __restrict__ hidden,
                                                const float* __restrict__ wq,
                                                const float* __restrict__ wk,
                                                const float* __restrict__ wv) {
    __shared__ char smem[GSMEM];
    int bx = blockIdx.x;
    int wsel = bx >> 3;
    int n0 = (bx & 7) * 128;
    const float* W = (wsel == 0) ? wq : (wsel == 1) ? wk : wv;
    float* C = (wsel == 0) ? g_q : (wsel == 1) ? g_k : g_v;
    int m0 = blockIdx.y * 128;

    float acc[4][4][4] = {};
    mma_gemm_tile(hidden, W, m0, n0, acc, smem);

    int lane = threadIdx.x & 31, wid = threadIdx.x >> 5;
    int wm = wid >> 2, wn = wid & 3;
    int g = lane >> 2, tg = lane & 3;
    #pragma unroll
    for (int mt = 0; mt < 4; mt++) {
        #pragma unroll
        for (int nt = 0; nt < 4; nt++) {
            int r0 = m0 + wm * 64 + mt * 16 + g;
            int c = n0 + wn * 32 + nt * 8 + tg * 2;
            int h = c >> 6, d = c & 63;
            int b0 = r0 >> 11, s0 = r0 & (S_ - 1);
            float2 v0 = {acc[mt][nt][0], acc[mt][nt][1]};
            *(float2*)&C[(((size_t)(b0 * NH + h) * S_ + s0) << 6) + d] = v0;
            int r1 = r0 + 8;
            int b1 = r1 >> 11, s1 = r1 & (S_ - 1);
            float2 v1 = {acc[mt][nt][2], acc[mt][nt][3]};
            *(float2*)&C[(((size_t)(b1 * NH + h) * S_ + s1) << 6) + d] = v1;
        }
    }
}

// output projection: out = g_ctx @ wo^T. grid (8, 64)
__global__ __launch_bounds__(256) void outproj_mma(const float* __restrict__ wo,
                                                   float* __restrict__ out) {
    __shared__ char smem[GSMEM];
    int n0 = blockIdx.x * 128;
    int m0 = blockIdx.y * 128;

    float acc[4][4][4] = {};
    mma_gemm_tile(g_ctx, wo, m0, n0, acc, smem);

    int lane = threadIdx.x & 31, wid = threadIdx.x >> 5;
    int wm = wid >> 2, wn = wid & 3;
    int g = lane >> 2, tg = lane & 3;
    #pragma unroll
    for (int mt = 0; mt < 4; mt++) {
        #pragma unroll
        for (int nt = 0; nt < 4; nt++) {
            int r0 = m0 + wm * 64 + mt * 16 + g;
            int c = n0 + wn * 32 + nt * 8 + tg * 2;
            float2 v0 = {acc[mt][nt][0], acc[mt][nt][1]};
            *(float2*)&out[(size_t)r0 * DM + c] = v0;
            float2 v1 = {acc[mt][nt][2], acc[mt][nt][3]};
            *(float2*)&out[(size_t)(r0 + 8) * DM + c] = v1;
        }
    }
}

// ---------------- flash attention fp32, 64x64 tiles, online softmax ----------------
#define PAD 68

__global__ __launch_bounds__(256) void attn_kernel(const float* __restrict__ rel_bias,
                                                   const float* __restrict__ mask) {
    extern __shared__ float sm[];
    float* Qs  = sm;
    float* Kt  = Qs + 64 * PAD;
    float* Vs  = Kt + 64 * PAD;
    float* Ps  = Vs + 64 * 64;
    float* rbh = Ps + 64 * PAD;
    float* mcl = rbh + 32;

    int tid = threadIdx.x;
    int tx = tid & 15, ty = tid >> 4;
    int q0 = blockIdx.x * 64, h = blockIdx.y, b = blockIdx.z;

    const float* qbase = g_q + ((size_t)(b * NH + h) * S_ + q0) * DK;
    const float* kbase = g_k + (size_t)(b * NH + h) * S_ * DK;
    const float* vbase = g_v + (size_t)(b * NH + h) * S_ * DK;
    const unsigned char* bkbase = g_bucket + ((size_t)b * S_ + q0) * S_;

    if (tid < 32) rbh[tid] = rel_bias[tid * NH + h];

    #pragma unroll
    for (int i = 0; i < 4; i++) {
        int idx = tid + i * 256;
        int r = idx >> 4, d4 = idx & 15;
        *(float4*)&Qs[r * PAD + d4 * 4] = *(const float4*)&qbase[r * 64 + d4 * 4];
    }

    float m_i[4], l_i[4], o[4][4];
    #pragma unroll
    for (int i = 0; i < 4; i++) {
        m_i[i] = -1e30f; l_i[i] = 0.f;
        #pragma unroll
        for (int j = 0; j < 4; j++) o[i][j] = 0.f;
    }

    for (int k0 = 0; k0 < S_; k0 += 64) {
        __syncthreads();
        #pragma unroll
        for (int i = 0; i < 4; i++) {
            int idx = tid + i * 256;
            int r = idx >> 4, d4 = idx & 15;
            float4 kv = *(const float4*)&kbase[(size_t)(k0 + r) * 64 + d4 * 4];
            Kt[(d4 * 4 + 0) * PAD + r] = kv.x;
            Kt[(d4 * 4 + 1) * PAD + r] = kv.y;
            Kt[(d4 * 4 + 2) * PAD + r] = kv.z;
            Kt[(d4 * 4 + 3) * PAD + r] = kv.w;
            *(float4*)&Vs[r * 64 + d4 * 4] = *(const float4*)&vbase[(size_t)(k0 + r) * 64 + d4 * 4];
        }
        if (tid < 64) mcl[tid] = -1000.0f * (1.0f - mask[b * S_ + k0 + tid]);
        __syncthreads();

        float s[4][4] = {};
        #pragma unroll
        for (int d = 0; d < 64; d++) {
            float a0 = Qs[(ty * 4 + 0) * PAD + d];
            float a1 = Qs[(ty * 4 + 1) * PAD + d];
            float a2 = Qs[(ty * 4 + 2) * PAD + d];
            float a3 = Qs[(ty * 4 + 3) * PAD + d];
            float4 bb = *(const float4*)&Kt[d * PAD + tx * 4];
            s[0][0] += a0 * bb.x; s[0][1] += a0 * bb.y; s[0][2] += a0 * bb.z; s[0][3] += a0 * bb.w;
            s[1][0] += a1 * bb.x; s[1][1] += a1 * bb.y; s[1][2] += a1 * bb.z; s[1][3] += a1 * bb.w;
            s[2][0] += a2 * bb.x; s[2][1] += a2 * bb.y; s[2][2] += a2 * bb.z; s[2][3] += a2 * bb.w;
            s[3][0] += a3 * bb.x; s[3][1] += a3 * bb.y; s[3][2] += a3 * bb.z; s[3][3] += a3 * bb.w;
        }

        float mc0 = mcl[tx * 4 + 0], mc1 = mcl[tx * 4 + 1], mc2 = mcl[tx * 4 + 2], mc3 = mcl[tx * 4 + 3];
        #pragma unroll
        for (int i = 0; i < 4; i++) {
            uchar4 bk = *(const uchar4*)(bkbase + (size_t)(ty * 4 + i) * S_ + k0 + tx * 4);
            s[i][0] += rbh[bk.x] + mc0;
            s[i][1] += rbh[bk.y] + mc1;
            s[i][2] += rbh[bk.z] + mc2;
            s[i][3] += rbh[bk.w] + mc3;
        }

        #pragma unroll
        for (int i = 0; i < 4; i++) {
            float rm = fmaxf(fmaxf(s[i][0], s[i][1]), fmaxf(s[i][2], s[i][3]));
            rm = fmaxf(rm, __shfl_xor_sync(0xffffffffu, rm, 1));
            rm = fmaxf(rm, __shfl_xor_sync(0xffffffffu, rm, 2));
            rm = fmaxf(rm, __shfl_xor_sync(0xffffffffu, rm, 4));
            rm = fmaxf(rm, __shfl_xor_sync(0xffffffffu, rm, 8));
            float mn = fmaxf(m_i[i], rm);
            float fac = __expf(m_i[i] - mn);
            m_i[i] = mn;
            float p0 = __expf(s[i][0] - mn);
            float p1 = __expf(s[i][1] - mn);
            float p2 = __expf(s[i][2] - mn);
            float p3 = __expf(s[i][3] - mn);
            float rs = p0 + p1 + p2 + p3;
            rs += __shfl_xor_sync(0xffffffffu, rs, 1);
            rs += __shfl_xor_sync(0xffffffffu, rs, 2);
            rs += __shfl_xor_sync(0xffffffffu, rs, 4);
            rs += __shfl_xor_sync(0xffffffffu, rs, 8);
            l_i[i] = l_i[i] * fac + rs;
            o[i][0] *= fac; o[i][1] *= fac; o[i][2] *= fac; o[i][3] *= fac;
            float4 pv = {p0, p1, p2, p3};
            *(float4*)&Ps[(ty * 4 + i) * PAD + tx * 4] = pv;
        }
        __syncthreads();

        #pragma unroll
        for (int k = 0; k < 64; k++) {
            float a0 = Ps[(ty * 4 + 0) * PAD + k];
            float a1 = Ps[(ty * 4 + 1) * PAD + k];
            float a2 = Ps[(ty * 4 + 2) * PAD + k];
            float a3 = Ps[(ty * 4 + 3) * PAD + k];
            float4 bb = *(const float4*)&Vs[k * 64 + tx * 4];
            o[0][0] += a0 * bb.x; o[0][1] += a0 * bb.y; o[0][2] += a0 * bb.z; o[0][3] += a0 * bb.w;
            o[1][0] += a1 * bb.x; o[1][1] += a1 * bb.y; o[1][2] += a1 * bb.z; o[1][3] += a1 * bb.w;
            o[2][0] += a2 * bb.x; o[2][1] += a2 * bb.y; o[2][2] += a2 * bb.z; o[2][3] += a2 * bb.w;
            o[3][0] += a3 * bb.x; o[3][1] += a3 * bb.y; o[3][2] += a3 * bb.z; o[3][3] += a3 * bb.w;
        }
    }

    float* cbase = g_ctx + ((size_t)(b * S_ + q0)) * INNER + h * DK;
    #pragma unroll
    for (int i = 0; i < 4; i++) {
        float inv = 1.0f / l_i[i];
        float4 v = {o[i][0] * inv, o[i][1] * inv, o[i][2] * inv, o[i][3] * inv};
        *(float4*)&cbase[(size_t)(ty * 4 + i) * INNER + tx * 4] = v;
    }
}

// ---------------- launch ----------------
static const int ATTN_SMEM = (64 * PAD * 3 + 64 * 64 + 32 + 64) * (int)sizeof(float);

extern "C" void kernel_launch(void* const* d_in, const int* in_sizes, int n_in,
                              void* d_out, int out_size) {
    const float* hidden    = (const float*)d_in[0];
    const int*   positions = (const int*)d_in[1];
    const float* mask      = (const float*)d_in[2];
    const float* wq        = (const float*)d_in[3];
    const float* wk        = (const float*)d_in[4];
    const float* wv        = (const float*)d_in[5];
    const float* wo        = (const float*)d_in[6];
    const float* rel_bias  = (const float*)d_in[7];
    float* out = (float*)d_out;

    cudaFuncSetAttribute(attn_kernel, cudaFuncAttributeMaxDynamicSharedMemorySize, ATTN_SMEM);

    int nb = B_ * S_ * S_;
    bucket_kernel<<<(nb + 255) / 256, 256>>>(positions);

    dim3 gproj(24, 64);
    proj_mma<<<gproj, 256>>>(hidden, wq, wk, wv);

    dim3 gattn(S_ / 64, NH, B_);
    attn_kernel<<<gattn, 256, ATTN_SMEM>>>(rel_bias, mask);

    dim3 gout(8, 64);
    outproj_mma<<<gout, 256>>>(wo, out);
}

// round 4
// speedup vs baseline: 2.3528x; 1.7829x over previous
#include <cuda_runtime.h>
#include <cuda_bf16.h>
#include <math.h>
#include <stdint.h>

#define B_    4
#define S_    2048
#define DM    1024
#define NH    16
#define DK    64
#define INNER 1024

// ---------------- scratch (static device globals; no allocation) ----------------
__device__ float g_q[(size_t)B_ * NH * S_ * DK];     // [B,H,S,DK]
__device__ float g_k[(size_t)B_ * NH * S_ * DK];
__device__ float g_v[(size_t)B_ * NH * S_ * DK];
__device__ float g_ctx[(size_t)B_ * S_ * INNER];     // [B,S,H*DK]
__device__ unsigned char g_bucket[(size_t)B_ * S_ * S_];  // [B,Sq,Sk]

// ================= bucket precompute =================
__global__ void bucket_kernel(const int* __restrict__ pos) {
    int idx = blockIdx.x * blockDim.x + threadIdx.x;
    if (idx >= B_ * S_ * S_) return;
    int k = idx & (S_ - 1);
    int q = (idx >> 11) & (S_ - 1);
    int b = idx >> 22;
    int rel = pos[b * S_ + k] - pos[b * S_ + q];
    int ret = (rel > 0) ? 16 : 0;
    int rp = rel < 0 ? -rel : rel;
    int bucket;
    if (rp < 8) {
        bucket = rp;
    } else {
        float v = logf((float)rp * 0.125f);
        v = v / 2.772588722239781f;
        v = v * 8.0f;
        bucket = 8 + (int)v;
        bucket = bucket < 15 ? bucket : 15;
    }
    g_bucket[idx] = (unsigned char)(ret + bucket);
}

// ================= shared mma helpers =================
__device__ __forceinline__ void mma16816(float* c, const uint32_t* a, const uint32_t* b) {
    asm volatile(
        "mma.sync.aligned.m16n8k16.row.col.f32.bf16.bf16.f32 "
        "{%0,%1,%2,%3}, {%4,%5,%6,%7}, {%8,%9}, {%0,%1,%2,%3};\n"
        : "+f"(c[0]), "+f"(c[1]), "+f"(c[2]), "+f"(c[3])
        : "r"(a[0]), "r"(a[1]), "r"(a[2]), "r"(a[3]), "r"(b[0]), "r"(b[1]));
}

__device__ __forceinline__ void split2(float x, float y, uint32_t& hi, uint32_t& lo) {
    __nv_bfloat162 h = __floats2bfloat162_rn(x, y);
    float rx = x - __bfloat162float(h.x);
    float ry = y - __bfloat162float(h.y);
    __nv_bfloat162 l = __floats2bfloat162_rn(rx, ry);
    hi = *(uint32_t*)&h;
    lo = *(uint32_t*)&l;
}

// ================= mma.sync bf16-split GEMM core (projections) =================
#define RS 80
#define AHI_OFF 0
#define ALO_OFF (128 * RS)
#define BHI_OFF (2 * 128 * RS)
#define BLO_OFF (3 * 128 * RS)
#define GSMEM   (4 * 128 * RS)

__device__ __forceinline__ void sts_split(char* hi, char* lo, float4 v) {
    uint32_t h0, l0, h1, l1;
    split2(v.x, v.y, h0, l0);
    split2(v.z, v.w, h1, l1);
    uint2 uh = {h0, h1};
    uint2 ul = {l0, l1};
    *(uint2*)hi = uh;
    *(uint2*)lo = ul;
}

__device__ __forceinline__ void mma_gemm_tile(const float* __restrict__ A,
                                              const float* __restrict__ W,
                                              int m0, int n0,
                                              float acc[4][4][4], char* smem) {
    int tid = threadIdx.x, lane = tid & 31, wid = tid >> 5;
    int wm = wid >> 2, wn = wid & 3;
    int g = lane >> 2, tg = lane & 3;

    float4 ra[4], rb[4];
    #pragma unroll
    for (int j = 0; j < 4; j++) {
        int idx = tid + j * 256;
        int row = idx >> 3, c4 = idx & 7;
        ra[j] = *(const float4*)&A[((size_t)(m0 + row) << 10) + c4 * 4];
        rb[j] = *(const float4*)&W[((size_t)(n0 + row) << 10) + c4 * 4];
    }

    #pragma unroll 1
    for (int chunk = 0; chunk < 32; chunk++) {
        __syncthreads();
        #pragma unroll
        for (int j = 0; j < 4; j++) {
            int idx = tid + j * 256;
            int row = idx >> 3, c4 = idx & 7;
            uint32_t off = row * RS + c4 * 8;
            sts_split(smem + AHI_OFF + off, smem + ALO_OFF + off, ra[j]);
            sts_split(smem + BHI_OFF + off, smem + BLO_OFF + off, rb[j]);
        }
        __syncthreads();
        if (chunk < 31) {
            int k0 = (chunk + 1) * 32;
            #pragma unroll
            for (int j = 0; j < 4; j++) {
                int idx = tid + j * 256;
                int row = idx >> 3, c4 = idx & 7;
                ra[j] = *(const float4*)&A[((size_t)(m0 + row) << 10) + k0 + c4 * 4];
                rb[j] = *(const float4*)&W[((size_t)(n0 + row) << 10) + k0 + c4 * 4];
            }
        }
        #pragma unroll
        for (int kk = 0; kk < 2; kk++) {
            int kb = (tg * 2 + kk * 16) * 2;
            uint32_t bh[4][2], bl[4][2];
            #pragma unroll
            for (int nt = 0; nt < 4; nt++) {
                uint32_t off = (wn * 32 + nt * 8 + g) * RS + kb;
                bh[nt][0] = *(const uint32_t*)(smem + BHI_OFF + off);
                bh[nt][1] = *(const uint32_t*)(smem + BHI_OFF + off + 16);
                bl[nt][0] = *(const uint32_t*)(smem + BLO_OFF + off);
                bl[nt][1] = *(const uint32_t*)(smem + BLO_OFF + off + 16);
            }
            #pragma unroll
            for (int mt = 0; mt < 4; mt++) {
                uint32_t offa = (wm * 64 + mt * 16 + g) * RS + kb;
                uint32_t ah[4], al[4];
                ah[0] = *(const uint32_t*)(smem + AHI_OFF + offa);
                ah[1] = *(const uint32_t*)(smem + AHI_OFF + offa + 8 * RS);
                ah[2] = *(const uint32_t*)(smem + AHI_OFF + offa + 16);
                ah[3] = *(const uint32_t*)(smem + AHI_OFF + offa + 8 * RS + 16);
                al[0] = *(const uint32_t*)(smem + ALO_OFF + offa);
                al[1] = *(const uint32_t*)(smem + ALO_OFF + offa + 8 * RS);
                al[2] = *(const uint32_t*)(smem + ALO_OFF + offa + 16);
                al[3] = *(const uint32_t*)(smem + ALO_OFF + offa + 8 * RS + 16);
                #pragma unroll
                for (int nt = 0; nt < 4; nt++) {
                    mma16816(acc[mt][nt], ah, bh[nt]);
                    mma16816(acc[mt][nt], al, bh[nt]);
                    mma16816(acc[mt][nt], ah, bl[nt]);
                }
            }
        }
    }
}

__global__ __launch_bounds__(256) void proj_mma(const float* __restrict__ hidden,
                                                const float* __restrict__ wq,
                                                const float* __restrict__ wk,
                                                const float* __restrict__ wv) {
    __shared__ char smem[GSMEM];
    int bx = blockIdx.x;
    int wsel = bx >> 3;
    int n0 = (bx & 7) * 128;
    const float* W = (wsel == 0) ? wq : (wsel == 1) ? wk : wv;
    float* C = (wsel == 0) ? g_q : (wsel == 1) ? g_k : g_v;
    int m0 = blockIdx.y * 128;

    float acc[4][4][4] = {};
    mma_gemm_tile(hidden, W, m0, n0, acc, smem);

    int lane = threadIdx.x & 31, wid = threadIdx.x >> 5;
    int wm = wid >> 2, wn = wid & 3;
    int g = lane >> 2, tg = lane & 3;
    #pragma unroll
    for (int mt = 0; mt < 4; mt++) {
        #pragma unroll
        for (int nt = 0; nt < 4; nt++) {
            int r0 = m0 + wm * 64 + mt * 16 + g;
            int c = n0 + wn * 32 + nt * 8 + tg * 2;
            int h = c >> 6, d = c & 63;
            int b0 = r0 >> 11, s0 = r0 & (S_ - 1);
            float2 v0 = {acc[mt][nt][0], acc[mt][nt][1]};
            *(float2*)&C[(((size_t)(b0 * NH + h) * S_ + s0) << 6) + d] = v0;
            int r1 = r0 + 8;
            int b1 = r1 >> 11, s1 = r1 & (S_ - 1);
            float2 v1 = {acc[mt][nt][2], acc[mt][nt][3]};
            *(float2*)&C[(((size_t)(b1 * NH + h) * S_ + s1) << 6) + d] = v1;
        }
    }
}

__global__ __launch_bounds__(256) void outproj_mma(const float* __restrict__ wo,
                                                   float* __restrict__ out) {
    __shared__ char smem[GSMEM];
    int n0 = blockIdx.x * 128;
    int m0 = blockIdx.y * 128;

    float acc[4][4][4] = {};
    mma_gemm_tile(g_ctx, wo, m0, n0, acc, smem);

    int lane = threadIdx.x & 31, wid = threadIdx.x >> 5;
    int wm = wid >> 2, wn = wid & 3;
    int g = lane >> 2, tg = lane & 3;
    #pragma unroll
    for (int mt = 0; mt < 4; mt++) {
        #pragma unroll
        for (int nt = 0; nt < 4; nt++) {
            int r0 = m0 + wm * 64 + mt * 16 + g;
            int c = n0 + wn * 32 + nt * 8 + tg * 2;
            float2 v0 = {acc[mt][nt][0], acc[mt][nt][1]};
            *(float2*)&out[(size_t)r0 * DM + c] = v0;
            float2 v1 = {acc[mt][nt][2], acc[mt][nt][3]};
            *(float2*)&out[(size_t)(r0 + 8) * DM + c] = v1;
        }
    }
}

// ================= tensor-core flash attention =================
// 64-q tile, 128 threads (4 warps x 16 q-rows). bf16 2-term split on QK^T and PV.
// smem: Khi/Klo [64 seq][72 d] bf16, Vthi/Vtlo [64 d][72 seq] bf16 (transposed),
// row stride 144B -> conflict-free fragment LDS (bank = 4g+tg).
#define KROWB 144               // 72 bf16 per row
#define AT_KHI 0
#define AT_KLO 9216
#define AT_VTH 18432
#define AT_VTL 27648
#define AT_MCL 36864            // float[64]
#define AT_RBH 37120            // float[32]
#define AT_SMEM 37248

__global__ __launch_bounds__(128, 3) void attn_mma(const float* __restrict__ rel_bias,
                                                   const float* __restrict__ mask) {
    __shared__ char sm[AT_SMEM];
    float* mcl = (float*)(sm + AT_MCL);
    float* rbh = (float*)(sm + AT_RBH);

    int tid = threadIdx.x, lane = tid & 31, wq = tid >> 5;
    int g = lane >> 2, tg = lane & 3;
    int q0 = blockIdx.x * 64, h = blockIdx.y, b = blockIdx.z;

    const float* kbase = g_k + (size_t)(b * NH + h) * S_ * DK;
    const float* vbase = g_v + (size_t)(b * NH + h) * S_ * DK;

    if (tid < 32) rbh[tid] = rel_bias[tid * NH + h];

    // ---- Q fragments in registers (hi/lo), rows r0 = q0+wq*16+g, r0+8 ----
    int r0 = q0 + wq * 16 + g;
    const float* qp = g_q + ((size_t)(b * NH + h) * S_ + r0) * DK;
    uint32_t qh[4][4], ql[4][4];
    #pragma unroll
    for (int kc = 0; kc < 4; kc++) {
        int c = kc * 16 + 2 * tg;
        float2 v00 = *(const float2*)&qp[c];            // a0: (g, c)
        float2 v10 = *(const float2*)&qp[8 * DK + c];   // a1: (g+8, c)
        float2 v01 = *(const float2*)&qp[c + 8];        // a2: (g, c+8)
        float2 v11 = *(const float2*)&qp[8 * DK + c + 8]; // a3
        split2(v00.x, v00.y, qh[kc][0], ql[kc][0]);
        split2(v10.x, v10.y, qh[kc][1], ql[kc][1]);
        split2(v01.x, v01.y, qh[kc][2], ql[kc][2]);
        split2(v11.x, v11.y, qh[kc][3], ql[kc][3]);
    }

    const unsigned char* bk0 = g_bucket + ((size_t)b * S_ + r0) * S_;
    const unsigned char* bk1 = bk0 + 8 * (size_t)S_;

    float o[8][4] = {};
    float m0 = -1e30f, m1 = -1e30f, l0 = 0.f, l1 = 0.f;

    #pragma unroll 1
    for (int k0 = 0; k0 < S_; k0 += 64) {
        __syncthreads();   // previous iter done reading staging
        // ---- stage K [seq][d] hi/lo ----
        #pragma unroll
        for (int j = 0; j < 8; j++) {
            int idx = tid + j * 128;
            int seq = idx >> 4, d4 = idx & 15;
            float4 kv = *(const float4*)&kbase[(size_t)(k0 + seq) * DK + d4 * 4];
            uint32_t h0, lo0, h1, lo1;
            split2(kv.x, kv.y, h0, lo0);
            split2(kv.z, kv.w, h1, lo1);
            uint2 uh = {h0, h1}, ul = {lo0, lo1};
            *(uint2*)(sm + AT_KHI + seq * KROWB + d4 * 8) = uh;
            *(uint2*)(sm + AT_KLO + seq * KROWB + d4 * 8) = ul;
        }
        // ---- stage V transposed: Vt[d][seq] hi/lo (2x2 register blocks) ----
        #pragma unroll
        for (int j = 0; j < 8; j++) {
            int d2 = (lane & 3) + 4 * j;         // 0..31 (d pair index)
            int sp = (lane >> 2) + 8 * wq;       // 0..31 (seq pair index)
            const float* vp = vbase + (size_t)(k0 + 2 * sp) * DK + 2 * d2;
            float2 va = *(const float2*)vp;
            float2 vb = *(const float2*)(vp + DK);
            uint32_t h0, lo0, h1, lo1;
            split2(va.x, vb.x, h0, lo0);   // Vt[2d2][2sp..2sp+1]
            split2(va.y, vb.y, h1, lo1);   // Vt[2d2+1][...]
            *(uint32_t*)(sm + AT_VTH + (2 * d2) * KROWB + sp * 4) = h0;
            *(uint32_t*)(sm + AT_VTH + (2 * d2 + 1) * KROWB + sp * 4) = h1;
            *(uint32_t*)(sm + AT_VTL + (2 * d2) * KROWB + sp * 4) = lo0;
            *(uint32_t*)(sm + AT_VTL + (2 * d2 + 1) * KROWB + sp * 4) = lo1;
        }
        if (tid < 64) mcl[tid] = -1000.0f * (1.0f - mask[b * S_ + k0 + tid]);
        __syncthreads();

        // ---- S = Q @ K^T : s[nt] = scores for cols nt*8+2tg(+1), rows r0/r0+8 ----
        float s[8][4] = {};
        #pragma unroll
        for (int kc = 0; kc < 4; kc++) {
            int kb = (kc * 16 + 2 * tg) * 2;
            #pragma unroll
            for (int nt = 0; nt < 8; nt++) {
                const char* ph = sm + AT_KHI + (nt * 8 + g) * KROWB + kb;
                const char* pl = sm + AT_KLO + (nt * 8 + g) * KROWB + kb;
                uint32_t bh[2] = {*(const uint32_t*)ph, *(const uint32_t*)(ph + 16)};
                uint32_t bl[2] = {*(const uint32_t*)pl, *(const uint32_t*)(pl + 16)};
                mma16816(s[nt], qh[kc], bh);
                mma16816(s[nt], ql[kc], bh);
                mma16816(s[nt], qh[kc], bl);
            }
        }

        // ---- bias (bucket LUT + mask col) ----
        #pragma unroll
        for (int nt = 0; nt < 8; nt++) {
            int col = k0 + nt * 8 + 2 * tg;
            uchar2 u0 = *(const uchar2*)(bk0 + col);
            uchar2 u1 = *(const uchar2*)(bk1 + col);
            float mc0 = mcl[nt * 8 + 2 * tg], mc1 = mcl[nt * 8 + 2 * tg + 1];
            s[nt][0] += rbh[u0.x] + mc0;
            s[nt][1] += rbh[u0.y] + mc1;
            s[nt][2] += rbh[u1.x] + mc0;
            s[nt][3] += rbh[u1.y] + mc1;
        }

        // ---- online softmax (rows r0, r0+8; reduce across tg group) ----
        float rm0 = -1e30f, rm1 = -1e30f;
        #pragma unroll
        for (int nt = 0; nt < 8; nt++) {
            rm0 = fmaxf(rm0, fmaxf(s[nt][0], s[nt][1]));
            rm1 = fmaxf(rm1, fmaxf(s[nt][2], s[nt][3]));
        }
        rm0 = fmaxf(rm0, __shfl_xor_sync(0xffffffffu, rm0, 1));
        rm0 = fmaxf(rm0, __shfl_xor_sync(0xffffffffu, rm0, 2));
        rm1 = fmaxf(rm1, __shfl_xor_sync(0xffffffffu, rm1, 1));
        rm1 = fmaxf(rm1, __shfl_xor_sync(0xffffffffu, rm1, 2));
        float mn0 = fmaxf(m0, rm0), mn1 = fmaxf(m1, rm1);
        float fac0 = __expf(m0 - mn0), fac1 = __expf(m1 - mn1);
        m0 = mn0; m1 = mn1;
        float rs0 = 0.f, rs1 = 0.f;
        #pragma unroll
        for (int nt = 0; nt < 8; nt++) {
            s[nt][0] = __expf(s[nt][0] - mn0);
            s[nt][1] = __expf(s[nt][1] - mn0);
            s[nt][2] = __expf(s[nt][2] - mn1);
            s[nt][3] = __expf(s[nt][3] - mn1);
            rs0 += s[nt][0] + s[nt][1];
            rs1 += s[nt][2] + s[nt][3];
        }
        rs0 += __shfl_xor_sync(0xffffffffu, rs0, 1);
        rs0 += __shfl_xor_sync(0xffffffffu, rs0, 2);
        rs1 += __shfl_xor_sync(0xffffffffu, rs1, 1);
        rs1 += __shfl_xor_sync(0xffffffffu, rs1, 2);
        l0 = l0 * fac0 + rs0;
        l1 = l1 * fac1 + rs1;
        #pragma unroll
        for (int dt = 0; dt < 8; dt++) {
            o[dt][0] *= fac0; o[dt][1] *= fac0;
            o[dt][2] *= fac1; o[dt][3] *= fac1;
        }

        // ---- O += P @ V : P A-frags come straight from score regs ----
        #pragma unroll
        for (int kc = 0; kc < 4; kc++) {
            uint32_t ah[4], al[4];
            split2(s[2 * kc][0],     s[2 * kc][1],     ah[0], al[0]);
            split2(s[2 * kc][2],     s[2 * kc][3],     ah[1], al[1]);
            split2(s[2 * kc + 1][0], s[2 * kc + 1][1], ah[2], al[2]);
            split2(s[2 * kc + 1][2], s[2 * kc + 1][3], ah[3], al[3]);
            int kb = (kc * 16 + 2 * tg) * 2;
            #pragma unroll
            for (int dt = 0; dt < 8; dt++) {
                const char* ph = sm + AT_VTH + (dt * 8 + g) * KROWB + kb;
                const char* pl = sm + AT_VTL + (dt * 8 + g) * KROWB + kb;
                uint32_t bh[2] = {*(const uint32_t*)ph, *(const uint32_t*)(ph + 16)};
                uint32_t bl[2] = {*(const uint32_t*)pl, *(const uint32_t*)(pl + 16)};
                mma16816(o[dt], ah, bh);
                mma16816(o[dt], al, bh);
                mma16816(o[dt], ah, bl);
            }
        }
    }

    // ---- epilogue: normalize, write ctx [B,S,H*DK] ----
    float inv0 = 1.0f / l0, inv1 = 1.0f / l1;
    float* cb = g_ctx + ((size_t)(b * S_ + r0)) * INNER + h * DK;
    #pragma unroll
    for (int dt = 0; dt < 8; dt++) {
        float2 v0 = {o[dt][0] * inv0, o[dt][1] * inv0};
        *(float2*)&cb[dt * 8 + 2 * tg] = v0;
        float2 v1 = {o[dt][2] * inv1, o[dt][3] * inv1};
        *(float2*)&cb[(size_t)8 * INNER + dt * 8 + 2 * tg] = v1;
    }
}

// ---------------- launch ----------------
extern "C" void kernel_launch(void* const* d_in, const int* in_sizes, int n_in,
                              void* d_out, int out_size) {
    const float* hidden    = (const float*)d_in[0];
    const int*   positions = (const int*)d_in[1];
    const float* mask      = (const float*)d_in[2];
    const float* wq        = (const float*)d_in[3];
    const float* wk        = (const float*)d_in[4];
    const float* wv        = (const float*)d_in[5];
    const float* wo        = (const float*)d_in[6];
    const float* rel_bias  = (const float*)d_in[7];
    float* out = (float*)d_out;

    int nb = B_ * S_ * S_;
    bucket_kernel<<<(nb + 255) / 256, 256>>>(positions);

    dim3 gproj(24, 64);
    proj_mma<<<gproj, 256>>>(hidden, wq, wk, wv);

    dim3 gattn(S_ / 64, NH, B_);
    attn_mma<<<gattn, 128>>>(rel_bias, mask);

    dim3 gout(8, 64);
    outproj_mma<<<gout, 256>>>(wo, out);
}

// round 5
// speedup vs baseline: 2.4203x; 1.0287x over previous
#include <cuda_runtime.h>
#include <cuda_bf16.h>
#include <math.h>
#include <stdint.h>

#define B_    4
#define S_    2048
#define DM    1024
#define NH    16
#define DK    64
#define INNER 1024

// ---------------- scratch (static device globals; no allocation) ----------------
__device__ __align__(256) float g_q[(size_t)B_ * NH * S_ * DK];            // fp32 [B,H,S,DK]
__device__ __align__(256) __nv_bfloat16 g_khi[(size_t)B_ * NH * S_ * DK];  // [B,H,S,DK]
__device__ __align__(256) __nv_bfloat16 g_klo[(size_t)B_ * NH * S_ * DK];
__device__ __align__(256) __nv_bfloat16 g_vthi[(size_t)B_ * NH * DK * S_]; // [B,H,DK,S] (transposed)
__device__ __align__(256) __nv_bfloat16 g_vtlo[(size_t)B_ * NH * DK * S_];
__device__ __align__(256) __nv_bfloat16 g_ctxhi[(size_t)B_ * S_ * INNER];  // [B,S,INNER]
__device__ __align__(256) __nv_bfloat16 g_ctxlo[(size_t)B_ * S_ * INNER];
__device__ __align__(256) __nv_bfloat16 g_hidhi[(size_t)B_ * S_ * DM];
__device__ __align__(256) __nv_bfloat16 g_hidlo[(size_t)B_ * S_ * DM];
__device__ __align__(256) __nv_bfloat16 g_wqhi[(size_t)DM * DM], g_wqlo[(size_t)DM * DM];
__device__ __align__(256) __nv_bfloat16 g_wkhi[(size_t)DM * DM], g_wklo[(size_t)DM * DM];
__device__ __align__(256) __nv_bfloat16 g_wvhi[(size_t)DM * DM], g_wvlo[(size_t)DM * DM];
__device__ __align__(256) __nv_bfloat16 g_wohi[(size_t)DM * DM], g_wolo[(size_t)DM * DM];
__device__ unsigned char g_bucket[(size_t)B_ * S_ * S_];
__device__ unsigned char g_lutb[256];

// ================= helpers =================
__device__ __forceinline__ void mma16816(float* c, const uint32_t* a, const uint32_t* b) {
    asm volatile(
        "mma.sync.aligned.m16n8k16.row.col.f32.bf16.bf16.f32 "
        "{%0,%1,%2,%3}, {%4,%5,%6,%7}, {%8,%9}, {%0,%1,%2,%3};\n"
        : "+f"(c[0]), "+f"(c[1]), "+f"(c[2]), "+f"(c[3])
        : "r"(a[0]), "r"(a[1]), "r"(a[2]), "r"(a[3]), "r"(b[0]), "r"(b[1]));
}

__device__ __forceinline__ void split2(float x, float y, uint32_t& hi, uint32_t& lo) {
    __nv_bfloat162 h = __floats2bfloat162_rn(x, y);
    float rx = x - __bfloat162float(h.x);
    float ry = y - __bfloat162float(h.y);
    __nv_bfloat162 l = __floats2bfloat162_rn(rx, ry);
    hi = *(uint32_t*)&h;
    lo = *(uint32_t*)&l;
}

__device__ __forceinline__ uint32_t smem_u32(const void* p) {
    uint32_t a;
    asm("{ .reg .u64 t; cvta.to.shared.u64 t, %1; cvt.u32.u64 %0, t; }" : "=r"(a) : "l"(p));
    return a;
}
__device__ __forceinline__ void cp16(uint32_t dst, const void* src) {
    asm volatile("cp.async.ca.shared.global [%0], [%1], 16;" :: "r"(dst), "l"(src) : "memory");
}
#define CP_COMMIT() asm volatile("cp.async.commit_group;" ::: "memory")
#define CP_WAIT1()  asm volatile("cp.async.wait_group 1;" ::: "memory")
#define CP_WAIT0()  asm volatile("cp.async.wait_group 0;" ::: "memory")

// ================= bucket LUT + bucket =================
__global__ void lut_kernel() {
    int rp = threadIdx.x;
    int bucket;
    if (rp < 8) {
        bucket = rp;
    } else {
        float v = logf((float)rp * 0.125f);
        v = v / 2.772588722239781f;
        v = v * 8.0f;
        bucket = 8 + (int)v;
        bucket = bucket < 15 ? bucket : 15;
    }
    g_lutb[rp] = (unsigned char)bucket;
}

__global__ void bucket_kernel(const int* __restrict__ pos) {
    int idx = blockIdx.x * blockDim.x + threadIdx.x;
    if (idx >= B_ * S_ * S_) return;
    int k = idx & (S_ - 1);
    int q = (idx >> 11) & (S_ - 1);
    int b = idx >> 22;
    int rel = pos[b * S_ + k] - pos[b * S_ + q];
    int ret = (rel > 0) ? 16 : 0;
    int rp = rel < 0 ? -rel : rel;
    int bucket = g_lutb[rp < 256 ? rp : 255];
    g_bucket[idx] = (unsigned char)(ret + bucket);
}

// ================= pre-split fp32 -> hi/lo bf16 =================
__global__ void presplit_kernel(const float4* __restrict__ src,
                                uint2* __restrict__ hi, uint2* __restrict__ lo, int n4) {
    int i = blockIdx.x * blockDim.x + threadIdx.x;
    if (i >= n4) return;
    float4 v = src[i];
    uint32_t h0, l0, h1, l1;
    split2(v.x, v.y, h0, l0);
    split2(v.z, v.w, h1, l1);
    uint2 uh = {h0, h1}, ul = {l0, l1};
    hi[i] = uh;
    lo[i] = ul;
}

// ================= bf16 double-buffered GEMM core =================
// C[M,N] = A @ B^T, block 128x128, 256 thr (2x4 warps), warp 64x32.
#define RS 80
#define SA_HI 0
#define SA_LO 10240
#define SB_HI 20480
#define SB_LO 30720
#define STAGE 40960
#define GDSMEM (2 * STAGE)

__device__ __forceinline__ void gemm_stage(int c, uint32_t bufo, uint32_t sb,
                                           const __nv_bfloat16* Ahi, const __nv_bfloat16* Alo,
                                           const __nv_bfloat16* Bhi, const __nv_bfloat16* Blo,
                                           int m0, int n0, int tid) {
    int k0 = c * 32;
    #pragma unroll
    for (int j = 0; j < 2; j++) {
        int idx = tid + j * 256;
        int row = idx >> 2, q = idx & 3;
        size_t ga = (size_t)(m0 + row) * DM + k0 + q * 8;
        size_t gb = (size_t)(n0 + row) * DM + k0 + q * 8;
        uint32_t so = sb + bufo + row * RS + q * 16;
        cp16(so + SA_HI, Ahi + ga);
        cp16(so + SA_LO, Alo + ga);
        cp16(so + SB_HI, Bhi + gb);
        cp16(so + SB_LO, Blo + gb);
    }
    CP_COMMIT();
}

__device__ __forceinline__ void gemm_core(const __nv_bfloat16* Ahi, const __nv_bfloat16* Alo,
                                          const __nv_bfloat16* Bhi, const __nv_bfloat16* Blo,
                                          int m0, int n0, float acc[4][4][4], char* smem) {
    uint32_t sb = smem_u32(smem);
    int tid = threadIdx.x, lane = tid & 31, wid = tid >> 5;
    int wm = wid >> 2, wn = wid & 3;
    int g = lane >> 2, tg = lane & 3;

    gemm_stage(0, 0, sb, Ahi, Alo, Bhi, Blo, m0, n0, tid);
    gemm_stage(1, STAGE, sb, Ahi, Alo, Bhi, Blo, m0, n0, tid);

    #pragma unroll 1
    for (int c = 0; c < 32; c++) {
        uint32_t bufo = (c & 1) * STAGE;
        if (c < 31) CP_WAIT1(); else CP_WAIT0();
        __syncthreads();
        const char* bb = smem + bufo;
        #pragma unroll
        for (int kk = 0; kk < 2; kk++) {
            int kb = (tg * 2 + kk * 16) * 2;
            uint32_t bh[4][2], bl[4][2];
            #pragma unroll
            for (int nt = 0; nt < 4; nt++) {
                uint32_t off = (wn * 32 + nt * 8 + g) * RS + kb;
                bh[nt][0] = *(const uint32_t*)(bb + SB_HI + off);
                bh[nt][1] = *(const uint32_t*)(bb + SB_HI + off + 16);
                bl[nt][0] = *(const uint32_t*)(bb + SB_LO + off);
                bl[nt][1] = *(const uint32_t*)(bb + SB_LO + off + 16);
            }
            #pragma unroll
            for (int mt = 0; mt < 4; mt++) {
                uint32_t offa = (wm * 64 + mt * 16 + g) * RS + kb;
                uint32_t ah[4], al[4];
                ah[0] = *(const uint32_t*)(bb + SA_HI + offa);
                ah[1] = *(const uint32_t*)(bb + SA_HI + offa + 8 * RS);
                ah[2] = *(const uint32_t*)(bb + SA_HI + offa + 16);
                ah[3] = *(const uint32_t*)(bb + SA_HI + offa + 8 * RS + 16);
                al[0] = *(const uint32_t*)(bb + SA_LO + offa);
                al[1] = *(const uint32_t*)(bb + SA_LO + offa + 8 * RS);
                al[2] = *(const uint32_t*)(bb + SA_LO + offa + 16);
                al[3] = *(const uint32_t*)(bb + SA_LO + offa + 8 * RS + 16);
                #pragma unroll
                for (int nt = 0; nt < 4; nt++) {
                    mma16816(acc[mt][nt], ah, bh[nt]);
                    mma16816(acc[mt][nt], al, bh[nt]);
                    mma16816(acc[mt][nt], ah, bl[nt]);
                }
            }
        }
        __syncthreads();
        if (c + 2 < 32) gemm_stage(c + 2, bufo, sb, Ahi, Alo, Bhi, Blo, m0, n0, tid);
    }
}

// QKV projection. grid (24, 64)
__global__ __launch_bounds__(256) void proj_mma() {
    extern __shared__ char smem[];
    int bx = blockIdx.x;
    int wsel = bx >> 3;
    int n0 = (bx & 7) * 128;
    int m0 = blockIdx.y * 128;
    const __nv_bfloat16* Bh = (wsel == 0) ? g_wqhi : (wsel == 1) ? g_wkhi : g_wvhi;
    const __nv_bfloat16* Bl = (wsel == 0) ? g_wqlo : (wsel == 1) ? g_wklo : g_wvlo;

    float acc[4][4][4] = {};
    gemm_core(g_hidhi, g_hidlo, Bh, Bl, m0, n0, acc, smem);

    int lane = threadIdx.x & 31, wid = threadIdx.x >> 5;
    int wm = wid >> 2, wn = wid & 3;
    int g = lane >> 2, tg = lane & 3;
    #pragma unroll
    for (int mt = 0; mt < 4; mt++) {
        #pragma unroll
        for (int nt = 0; nt < 4; nt++) {
            int r0 = m0 + wm * 64 + mt * 16 + g;
            int r1 = r0 + 8;
            int c = n0 + wn * 32 + nt * 8 + tg * 2;
            int h = c >> 6, d = c & 63;
            int b0 = r0 >> 11, s0 = r0 & (S_ - 1);
            int b1 = r1 >> 11, s1 = r1 & (S_ - 1);
            float a0 = acc[mt][nt][0], a1 = acc[mt][nt][1];
            float a2 = acc[mt][nt][2], a3 = acc[mt][nt][3];
            if (wsel == 0) {
                float2 v0 = {a0, a1};
                *(float2*)&g_q[(((size_t)(b0 * NH + h) * S_ + s0) << 6) + d] = v0;
                float2 v1 = {a2, a3};
                *(float2*)&g_q[(((size_t)(b1 * NH + h) * S_ + s1) << 6) + d] = v1;
            } else if (wsel == 1) {
                uint32_t h0, l0, h1, l1;
                split2(a0, a1, h0, l0);
                split2(a2, a3, h1, l1);
                size_t o0 = (((size_t)(b0 * NH + h) * S_ + s0) << 6) + d;
                size_t o1 = (((size_t)(b1 * NH + h) * S_ + s1) << 6) + d;
                *(uint32_t*)&g_khi[o0] = h0; *(uint32_t*)&g_klo[o0] = l0;
                *(uint32_t*)&g_khi[o1] = h1; *(uint32_t*)&g_klo[o1] = l1;
            } else {
                // V transposed: Vt[b,h,d,s]
                size_t base0 = ((size_t)(b0 * NH + h) * DK + d) * S_;
                size_t base1 = ((size_t)(b1 * NH + h) * DK + d) * S_;
                #pragma unroll
                for (int e = 0; e < 4; e++) {
                    float x = acc[mt][nt][e];
                    __nv_bfloat16 hh = __float2bfloat16(x);
                    __nv_bfloat16 ll = __float2bfloat16(x - __bfloat162float(hh));
                    size_t o = (e < 2 ? base0 + s0 : base1 + s1) + (size_t)(e & 1) * S_;
                    g_vthi[o] = hh;
                    g_vtlo[o] = ll;
                }
            }
        }
    }
}

// output projection: out = ctx @ wo^T. grid (8, 64)
__global__ __launch_bounds__(256) void outproj_mma(float* __restrict__ out) {
    extern __shared__ char smem[];
    int n0 = blockIdx.x * 128;
    int m0 = blockIdx.y * 128;

    float acc[4][4][4] = {};
    gemm_core(g_ctxhi, g_ctxlo, g_wohi, g_wolo, m0, n0, acc, smem);

    int lane = threadIdx.x & 31, wid = threadIdx.x >> 5;
    int wm = wid >> 2, wn = wid & 3;
    int g = lane >> 2, tg = lane & 3;
    #pragma unroll
    for (int mt = 0; mt < 4; mt++) {
        #pragma unroll
        for (int nt = 0; nt < 4; nt++) {
            int r0 = m0 + wm * 64 + mt * 16 + g;
            int c = n0 + wn * 32 + nt * 8 + tg * 2;
            float2 v0 = {acc[mt][nt][0], acc[mt][nt][1]};
            *(float2*)&out[(size_t)r0 * DM + c] = v0;
            float2 v1 = {acc[mt][nt][2], acc[mt][nt][3]};
            *(float2*)&out[(size_t)(r0 + 8) * DM + c] = v1;
        }
    }
}

// ================= tensor-core flash attention (cp.async double-buffered) =================
#define KROWB 144
#define AT_KHI 0
#define AT_KLO 9216
#define AT_VTH 18432
#define AT_VTL 27648
#define ATSTAGE 36864
#define AT_MCL (2 * ATSTAGE)          // 2 x 64 floats
#define AT_RBH (AT_MCL + 512)         // 32 floats
#define AT_DSMEM (AT_RBH + 128)

__global__ __launch_bounds__(128, 2) void attn_mma(const float* __restrict__ rel_bias,
                                                   const float* __restrict__ mask) {
    extern __shared__ char sm[];
    float* rbh = (float*)(sm + AT_RBH);
    uint32_t sb = smem_u32(sm);

    int tid = threadIdx.x, lane = tid & 31, wrp = tid >> 5;
    int g = lane >> 2, tg = lane & 3;
    int q0 = blockIdx.x * 64, h = blockIdx.y, b = blockIdx.z;

    const __nv_bfloat16* khi = g_khi + (size_t)(b * NH + h) * S_ * DK;
    const __nv_bfloat16* klo = g_klo + (size_t)(b * NH + h) * S_ * DK;
    const __nv_bfloat16* vth = g_vthi + (size_t)(b * NH + h) * DK * S_;
    const __nv_bfloat16* vtl = g_vtlo + (size_t)(b * NH + h) * DK * S_;
    const float* maskp = mask + b * S_;

    if (tid < 32) rbh[tid] = rel_bias[tid * NH + h];

    // stage K/V tile i via cp.async
    auto stage = [&](int i) {
        int k0 = i * 64;
        uint32_t bufo = (i & 1) * ATSTAGE;
        #pragma unroll
        for (int j = 0; j < 4; j++) {
            int idx = tid + j * 128;
            int r = idx >> 3, q = idx & 7;
            uint32_t so = sb + bufo + r * KROWB + q * 16;
            cp16(so + AT_KHI, khi + (size_t)(k0 + r) * DK + q * 8);
            cp16(so + AT_KLO, klo + (size_t)(k0 + r) * DK + q * 8);
            cp16(so + AT_VTH, vth + (size_t)r * S_ + k0 + q * 8);
            cp16(so + AT_VTL, vtl + (size_t)r * S_ + k0 + q * 8);
        }
        if (tid < 16) cp16(sb + AT_MCL + (i & 1) * 256 + tid * 16, maskp + k0 + tid * 4);
        CP_COMMIT();
    };

    // Q fragments (hi/lo) in registers
    int r0 = q0 + wrp * 16 + g;
    const float* qp = g_q + ((size_t)(b * NH + h) * S_ + r0) * DK;
    uint32_t qh[4][4], ql[4][4];
    #pragma unroll
    for (int kc = 0; kc < 4; kc++) {
        int c = kc * 16 + 2 * tg;
        float2 v00 = *(const float2*)&qp[c];
        float2 v10 = *(const float2*)&qp[8 * DK + c];
        float2 v01 = *(const float2*)&qp[c + 8];
        float2 v11 = *(const float2*)&qp[8 * DK + c + 8];
        split2(v00.x, v00.y, qh[kc][0], ql[kc][0]);
        split2(v10.x, v10.y, qh[kc][1], ql[kc][1]);
        split2(v01.x, v01.y, qh[kc][2], ql[kc][2]);
        split2(v11.x, v11.y, qh[kc][3], ql[kc][3]);
    }

    const unsigned char* bk0 = g_bucket + ((size_t)b * S_ + r0) * S_;
    const unsigned char* bk1 = bk0 + 8 * (size_t)S_;

    float o[8][4] = {};
    float m0 = -1e30f, m1 = -1e30f, l0 = 0.f, l1 = 0.f;

    stage(0);
    stage(1);

    #pragma unroll 1
    for (int i = 0; i < 32; i++) {
        int k0 = i * 64;
        uint32_t bufo = (i & 1) * ATSTAGE;
        if (i < 31) CP_WAIT1(); else CP_WAIT0();
        __syncthreads();
        const char* bb = sm + bufo;
        const float* mclf = (const float*)(sm + AT_MCL + (i & 1) * 256);

        // ---- S = Q @ K^T ----
        float s[8][4] = {};
        #pragma unroll
        for (int kc = 0; kc < 4; kc++) {
            int kb = (kc * 16 + 2 * tg) * 2;
            #pragma unroll
            for (int nt = 0; nt < 8; nt++) {
                const char* ph = bb + AT_KHI + (nt * 8 + g) * KROWB + kb;
                const char* pl = bb + AT_KLO + (nt * 8 + g) * KROWB + kb;
                uint32_t bhf[2] = {*(const uint32_t*)ph, *(const uint32_t*)(ph + 16)};
                uint32_t blf[2] = {*(const uint32_t*)pl, *(const uint32_t*)(pl + 16)};
                mma16816(s[nt], qh[kc], bhf);
                mma16816(s[nt], ql[kc], bhf);
                mma16816(s[nt], qh[kc], blf);
            }
        }

        // ---- bias ----
        #pragma unroll
        for (int nt = 0; nt < 8; nt++) {
            int col = k0 + nt * 8 + 2 * tg;
            uchar2 u0 = *(const uchar2*)(bk0 + col);
            uchar2 u1 = *(const uchar2*)(bk1 + col);
            float mv0 = mclf[nt * 8 + 2 * tg], mv1 = mclf[nt * 8 + 2 * tg + 1];
            float mc0 = -1000.0f + 1000.0f * mv0;
            float mc1 = -1000.0f + 1000.0f * mv1;
            s[nt][0] += rbh[u0.x] + mc0;
            s[nt][1] += rbh[u0.y] + mc1;
            s[nt][2] += rbh[u1.x] + mc0;
            s[nt][3] += rbh[u1.y] + mc1;
        }

        // ---- online softmax ----
        float rm0 = -1e30f, rm1 = -1e30f;
        #pragma unroll
        for (int nt = 0; nt < 8; nt++) {
            rm0 = fmaxf(rm0, fmaxf(s[nt][0], s[nt][1]));
            rm1 = fmaxf(rm1, fmaxf(s[nt][2], s[nt][3]));
        }
        rm0 = fmaxf(rm0, __shfl_xor_sync(0xffffffffu, rm0, 1));
        rm0 = fmaxf(rm0, __shfl_xor_sync(0xffffffffu, rm0, 2));
        rm1 = fmaxf(rm1, __shfl_xor_sync(0xffffffffu, rm1, 1));
        rm1 = fmaxf(rm1, __shfl_xor_sync(0xffffffffu, rm1, 2));
        float mn0 = fmaxf(m0, rm0), mn1 = fmaxf(m1, rm1);
        float fac0 = __expf(m0 - mn0), fac1 = __expf(m1 - mn1);
        m0 = mn0; m1 = mn1;
        float rs0 = 0.f, rs1 = 0.f;
        #pragma unroll
        for (int nt = 0; nt < 8; nt++) {
            s[nt][0] = __expf(s[nt][0] - mn0);
            s[nt][1] = __expf(s[nt][1] - mn0);
            s[nt][2] = __expf(s[nt][2] - mn1);
            s[nt][3] = __expf(s[nt][3] - mn1);
            rs0 += s[nt][0] + s[nt][1];
            rs1 += s[nt][2] + s[nt][3];
        }
        rs0 += __shfl_xor_sync(0xffffffffu, rs0, 1);
        rs0 += __shfl_xor_sync(0xffffffffu, rs0, 2);
        rs1 += __shfl_xor_sync(0xffffffffu, rs1, 1);
        rs1 += __shfl_xor_sync(0xffffffffu, rs1, 2);
        l0 = l0 * fac0 + rs0;
        l1 = l1 * fac1 + rs1;
        #pragma unroll
        for (int dt = 0; dt < 8; dt++) {
            o[dt][0] *= fac0; o[dt][1] *= fac0;
            o[dt][2] *= fac1; o[dt][3] *= fac1;
        }

        // ---- O += P @ V ----
        #pragma unroll
        for (int kc = 0; kc < 4; kc++) {
            uint32_t ah[4], al[4];
            split2(s[2 * kc][0],     s[2 * kc][1],     ah[0], al[0]);
            split2(s[2 * kc][2],     s[2 * kc][3],     ah[1], al[1]);
            split2(s[2 * kc + 1][0], s[2 * kc + 1][1], ah[2], al[2]);
            split2(s[2 * kc + 1][2], s[2 * kc + 1][3], ah[3], al[3]);
            int kb = (kc * 16 + 2 * tg) * 2;
            #pragma unroll
            for (int dt = 0; dt < 8; dt++) {
                const char* ph = bb + AT_VTH + (dt * 8 + g) * KROWB + kb;
                const char* pl = bb + AT_VTL + (dt * 8 + g) * KROWB + kb;
                uint32_t bhf[2] = {*(const uint32_t*)ph, *(const uint32_t*)(ph + 16)};
                uint32_t blf[2] = {*(const uint32_t*)pl, *(const uint32_t*)(pl + 16)};
                mma16816(o[dt], ah, bhf);
                mma16816(o[dt], al, bhf);
                mma16816(o[dt], ah, blf);
            }
        }
        __syncthreads();
        if (i + 2 < 32) stage(i + 2);
    }

    // ---- epilogue: normalize, write split ctx ----
    float inv0 = 1.0f / l0, inv1 = 1.0f / l1;
    size_t cb0 = ((size_t)(b * S_ + r0)) * INNER + h * DK;
    size_t cb1 = cb0 + (size_t)8 * INNER;
    #pragma unroll
    for (int dt = 0; dt < 8; dt++) {
        uint32_t hh, ll;
        split2(o[dt][0] * inv0, o[dt][1] * inv0, hh, ll);
        *(uint32_t*)&g_ctxhi[cb0 + dt * 8 + 2 * tg] = hh;
        *(uint32_t*)&g_ctxlo[cb0 + dt * 8 + 2 * tg] = ll;
        split2(o[dt][2] * inv1, o[dt][3] * inv1, hh, ll);
        *(uint32_t*)&g_ctxhi[cb1 + dt * 8 + 2 * tg] = hh;
        *(uint32_t*)&g_ctxlo[cb1 + dt * 8 + 2 * tg] = ll;
    }
}

// ---------------- launch ----------------
extern "C" void kernel_launch(void* const* d_in, const int* in_sizes, int n_in,
                              void* d_out, int out_size) {
    const float* hidden    = (const float*)d_in[0];
    const int*   positions = (const int*)d_in[1];
    const float* mask      = (const float*)d_in[2];
    const float* wq        = (const float*)d_in[3];
    const float* wk        = (const float*)d_in[4];
    const float* wv        = (const float*)d_in[5];
    const float* wo        = (const float*)d_in[6];
    const float* rel_bias  = (const float*)d_in[7];
    float* out = (float*)d_out;

    cudaFuncSetAttribute(proj_mma, cudaFuncAttributeMaxDynamicSharedMemorySize, GDSMEM);
    cudaFuncSetAttribute(outproj_mma, cudaFuncAttributeMaxDynamicSharedMemorySize, GDSMEM);
    cudaFuncSetAttribute(attn_mma, cudaFuncAttributeMaxDynamicSharedMemorySize, AT_DSMEM);

    // bucket LUT + buckets
    lut_kernel<<<1, 256>>>();
    int nb = B_ * S_ * S_;
    bucket_kernel<<<(nb + 255) / 256, 256>>>(positions);

    // pre-split hidden + weights
    {
        __nv_bfloat16 *hh, *hl, *qh_, *ql_, *kh, *kl, *vh, *vl, *oh, *ol;
        cudaGetSymbolAddress((void**)&hh, g_hidhi);
        cudaGetSymbolAddress((void**)&hl, g_hidlo);
        cudaGetSymbolAddress((void**)&qh_, g_wqhi);
        cudaGetSymbolAddress((void**)&ql_, g_wqlo);
        cudaGetSymbolAddress((void**)&kh, g_wkhi);
        cudaGetSymbolAddress((void**)&kl, g_wklo);
        cudaGetSymbolAddress((void**)&vh, g_wvhi);
        cudaGetSymbolAddress((void**)&vl, g_wvlo);
        cudaGetSymbolAddress((void**)&oh, g_wohi);
        cudaGetSymbolAddress((void**)&ol, g_wolo);
        int nh4 = B_ * S_ * DM / 4;
        presplit_kernel<<<(nh4 + 255) / 256, 256>>>((const float4*)hidden, (uint2*)hh, (uint2*)hl, nh4);
        int nw4 = DM * DM / 4;
        presplit_kernel<<<(nw4 + 255) / 256, 256>>>((const float4*)wq, (uint2*)qh_, (uint2*)ql_, nw4);
        presplit_kernel<<<(nw4 + 255) / 256, 256>>>((const float4*)wk, (uint2*)kh, (uint2*)kl, nw4);
        presplit_kernel<<<(nw4 + 255) / 256, 256>>>((const float4*)wv, (uint2*)vh, (uint2*)vl, nw4);
        presplit_kernel<<<(nw4 + 255) / 256, 256>>>((const float4*)wo, (uint2*)oh, (uint2*)ol, nw4);
    }

    dim3 gproj(24, 64);
    proj_mma<<<gproj, 256, GDSMEM>>>();

    dim3 gattn(S_ / 64, NH, B_);
    attn_mma<<<gattn, 128, AT_DSMEM>>>(rel_bias, mask);

    dim3 gout(8, 64);
    outproj_mma<<<gout, 256, GDSMEM>>>(out);
}